// round 15
// baseline (speedup 1.0000x reference)
#include <cuda_runtime.h>
#include <cuda_bf16.h>

// NURBS surface evaluation, degree 3 x 3, 32x32 control points, uniform
// clamped knots. S*F = 32 slices, P = 200000 points each.
//
// R14: R9's LDS.128 gather kept; occupancy recovered.
//  * PPT 8 -> 4 (single 4-point output group live -> fewer registers).
//  * __launch_bounds__(256, 4): cap 64 regs -> 4 CTAs/SM -> 32 warps/SM
//    (regs and smem both exactly fit: 64*256*4 = 64K regs, 4*51.2KB smem).
//  * Gather: packed-xyz rows, 4 pre-shifted smem copies so every row read is
//    3 aligned LDS.128 (192B/pt, zero waste); row stride 100 floats.

#define SFCOUNT 32
#define NCP     32
#define RSTRIDE 100          // floats per row in each copy (multiple of 4)
#define COPYSZ  (NCP * RSTRIDE)
#define SMEMSZ  (4 * COPYSZ * sizeof(float))   // 51200 B
#define PPT     4            // points per thread
#define TPB     256

__device__ __forceinline__ void eval_basis(float uu, float b[4], float d[4], int& si_out)
{
    float x  = uu * 29.0f;
    float fs = floorf(x);
    int   si = (int)fs;
    si = max(0, min(si, 28));
    fs = (float)si;

    float t  = x - fs;        // left1
    float r1 = 1.0f - t;      // right1

    float km1 = (float)max(si - 1, 0);
    float km2 = (float)max(si - 2, 0);
    float kp2 = (float)min(si + 2, 29);
    float kp3 = (float)min(si + 3, 29);
    float left2  = x - km1;
    float left3  = x - km2;
    float right2 = kp2 - x;
    float right3 = kp3 - x;

    // All Cox-de Boor denominators in {1,2,3}, selected by span.
    bool e0  = (si == 0);
    bool e1  = (si == 1);
    bool e27 = (si == 27);
    bool e28 = (si == 28);
    const float third = 1.0f / 3.0f;
    float inv20 = e0  ? 1.0f : 0.5f;
    float inv21 = e28 ? 1.0f : 0.5f;
    float inv30 = e0  ? 1.0f : (e1  ? 0.5f : third);
    float inv31 = (e0 || e28) ? 0.5f : third;
    float inv32 = e28 ? 1.0f : (e27 ? 0.5f : third);

    float tA  = r1 * inv20;
    float B20 = r1 * tA;
    float sv  = left2 * tA;
    float tB  = t * inv21;
    float B21 = fmaf(right2, tB, sv);
    float B22 = t * tB;

    float t0 = B20 * inv30;
    b[0] = r1 * t0;
    sv   = left3 * t0;
    float t1 = B21 * inv31;
    b[1] = fmaf(right2, t1, sv);
    sv   = left2 * t1;
    float t2 = B22 * inv32;
    b[2] = fmaf(right3, t2, sv);
    b[3] = t * t2;

    d[0] = -t0;
    d[1] = t0 - t1;
    d[2] = t1 - t2;
    d[3] = t2;

    si_out = si;
}

__global__ __launch_bounds__(TPB, 4)
void nurbs_kernel(const float* __restrict__ ev,
                  const float* __restrict__ cp,
                  float* __restrict__ out,
                  int P)
{
    extern __shared__ float scp[];   // [4 copies][32 rows][RSTRIDE]

    const int sf = blockIdx.y;
    const float* cpb = cp + (size_t)sf * (NCP * NCP * 3);

    // Stage CPs: packed xyz rows, 4 shifted copies for LDS.128 alignment.
    for (int k = threadIdx.x; k < NCP * NCP; k += TPB) {
        int iu = k >> 5;
        int iv = k & 31;
        float x = cpb[3 * k + 0];
        float y = cpb[3 * k + 1];
        float z = cpb[3 * k + 2];
#pragma unroll
        for (int m = 0; m < 4; m++) {
            float* row = scp + (m * NCP + iu) * RSTRIDE + m + 3 * iv;
            row[0] = x; row[1] = y; row[2] = z;
        }
    }
    __syncthreads();

    const int p0 = (blockIdx.x * TPB + threadIdx.x) * PPT;
    if (p0 >= P) return;   // P % 4 == 0: whole group valid or whole group out

    const size_t slice = (size_t)sf * P;

    const float4* ev4 = reinterpret_cast<const float4*>(ev + (slice + p0) * 2);
    float4 e0v = ev4[0];
    float4 e1v = ev4[1];
    float uvu[4] = {e0v.x, e0v.z, e1v.x, e1v.z};
    float uvv[4] = {e0v.y, e0v.w, e1v.y, e1v.w};

    float4 outpt[3];
    float4 outn [3];
    float* rp = reinterpret_cast<float*>(outpt);
    float* rn = reinterpret_cast<float*>(outn);

#pragma unroll
    for (int q = 0; q < 4; q++) {
        float bu[4], du[4], bv[4], dv[4];
        int su, svi;
        eval_basis(uvu[q], bu, du, su);
        eval_basis(uvv[q], bv, dv, svi);

        float px = 0.f, py = 0.f, pz = 0.f;
        float ax = 0.f, ay = 0.f, az = 0.f;
        float cx = 0.f, cy = 0.f, cz = 0.f;

        const int m = svi & 3;
        // float index divisible by 4 by construction
        const float4* base = reinterpret_cast<const float4*>(
            scp + (m * NCP + su) * RSTRIDE + m + 3 * svi);

#pragma unroll
        for (int i = 0; i < 4; i++) {
            const float4* r = base + i * (RSTRIDE / 4);
            float4 f0 = r[0];
            float4 f1 = r[1];
            float4 f2 = r[2];
            // f0 = x0 y0 z0 x1 | f1 = y1 z1 x2 y2 | f2 = z2 x3 y3 z3

            float rx = fmaf(bv[3], f2.y, fmaf(bv[2], f1.z, fmaf(bv[1], f0.w, bv[0] * f0.x)));
            float ry = fmaf(bv[3], f2.z, fmaf(bv[2], f1.w, fmaf(bv[1], f1.x, bv[0] * f0.y)));
            float rz = fmaf(bv[3], f2.w, fmaf(bv[2], f2.x, fmaf(bv[1], f1.y, bv[0] * f0.z)));
            float qx = fmaf(dv[3], f2.y, fmaf(dv[2], f1.z, fmaf(dv[1], f0.w, dv[0] * f0.x)));
            float qy = fmaf(dv[3], f2.z, fmaf(dv[2], f1.w, fmaf(dv[1], f1.x, dv[0] * f0.y)));
            float qz = fmaf(dv[3], f2.w, fmaf(dv[2], f2.x, fmaf(dv[1], f1.y, dv[0] * f0.z)));

            px = fmaf(bu[i], rx, px);
            py = fmaf(bu[i], ry, py);
            pz = fmaf(bu[i], rz, pz);
            ax = fmaf(du[i], rx, ax);
            ay = fmaf(du[i], ry, ay);
            az = fmaf(du[i], rz, az);
            cx = fmaf(bu[i], qx, cx);
            cy = fmaf(bu[i], qy, cy);
            cz = fmaf(bu[i], qz, cz);
        }

        float nx = fmaf(ay, cz, -(az * cy));
        float ny = fmaf(az, cx, -(ax * cz));
        float nz = fmaf(ax, cy, -(ay * cx));

        float n2 = fmaf(nx, nx, fmaf(ny, ny, nz * nz));
        n2 = fmaxf(n2, 1.0e-30f);
        float h = 0.5f * n2;
        float y = __uint_as_float(0x5f3759dfu - (__float_as_uint(n2) >> 1));
        y = y * fmaf(-h, y * y, 1.5f);
        y = y * fmaf(-h, y * y, 1.5f);

        rp[q * 3 + 0] = px;
        rp[q * 3 + 1] = py;
        rp[q * 3 + 2] = pz;
        rn[q * 3 + 0] = nx * y;
        rn[q * 3 + 1] = ny * y;
        rn[q * 3 + 2] = nz * y;
    }

    float4* opt = reinterpret_cast<float4*>(out + (slice + p0) * 3);
    opt[0] = outpt[0];
    opt[1] = outpt[1];
    opt[2] = outpt[2];
    float4* onr = reinterpret_cast<float4*>(out + (size_t)SFCOUNT * P * 3 +
                                            (slice + p0) * 3);
    onr[0] = outn[0];
    onr[1] = outn[1];
    onr[2] = outn[2];
}

extern "C" void kernel_launch(void* const* d_in, const int* in_sizes, int n_in,
                              void* d_out, int out_size)
{
    const float* ev = (const float*)d_in[0];   // [S,F,P,2] f32
    const float* cp = (const float*)d_in[1];   // [S,F,32,32,3] f32
    float* out = (float*)d_out;                // [2,S,F,P,3] f32 (pt, normals)

    const int P = in_sizes[0] / (SFCOUNT * 2);

    cudaFuncSetAttribute(nurbs_kernel,
                         cudaFuncAttributeMaxDynamicSharedMemorySize,
                         (int)SMEMSZ);

    const int pts_per_block = TPB * PPT;
    dim3 grid((P + pts_per_block - 1) / pts_per_block, SFCOUNT);
    nurbs_kernel<<<grid, TPB, SMEMSZ>>>(ev, cp, out, P);
}

// round 17
// speedup vs baseline: 1.7111x; 1.7111x over previous
#include <cuda_runtime.h>
#include <cuda_bf16.h>

// NURBS surface evaluation, degree 3 x 3, 32x32 control points, uniform
// clamped knots. S*F = 32 slices, P = 200000 points each.
//
// R16 == R15 re-run (previous bench died to container infra, no data):
//  * PPT = 2 -> small live state, fits 64 regs -> __launch_bounds__(256,4)
//    gives 4 CTAs/SM (204.8KB smem) = 32 warps/SM, no spilling.
//  * Persistent CTAs: 18 blocks per slice (576 total ~ one wave at occ 4),
//    each strides over ~11264 points, so the 4-copy smem staging is
//    amortized to ~0.05 wf/pt.
//  * Gather from R9: packed-xyz rows, 4 pre-shifted copies so each patch
//    row is 3 aligned LDS.128 (192B/pt, zero waste), row stride 100 floats.

#define SFCOUNT 32
#define NCP     32
#define RSTRIDE 100          // floats per row in each copy (multiple of 4)
#define COPYSZ  (NCP * RSTRIDE)
#define SMEMSZ  (4 * COPYSZ * sizeof(float))   // 51200 B
#define TPB     256
#define NBX     18           // blocks per slice (576 CTAs ~ 148 SMs * 4)

__device__ __forceinline__ void eval_basis(float uu, float b[4], float d[4], int& si_out)
{
    float x  = uu * 29.0f;
    float fs = floorf(x);
    int   si = (int)fs;
    si = max(0, min(si, 28));
    fs = (float)si;

    float t  = x - fs;        // left1
    float r1 = 1.0f - t;      // right1

    float km1 = (float)max(si - 1, 0);
    float km2 = (float)max(si - 2, 0);
    float kp2 = (float)min(si + 2, 29);
    float kp3 = (float)min(si + 3, 29);
    float left2  = x - km1;
    float left3  = x - km2;
    float right2 = kp2 - x;
    float right3 = kp3 - x;

    // All Cox-de Boor denominators in {1,2,3}, selected by span.
    bool e0  = (si == 0);
    bool e1  = (si == 1);
    bool e27 = (si == 27);
    bool e28 = (si == 28);
    const float third = 1.0f / 3.0f;
    float inv20 = e0  ? 1.0f : 0.5f;
    float inv21 = e28 ? 1.0f : 0.5f;
    float inv30 = e0  ? 1.0f : (e1  ? 0.5f : third);
    float inv31 = (e0 || e28) ? 0.5f : third;
    float inv32 = e28 ? 1.0f : (e27 ? 0.5f : third);

    float tA  = r1 * inv20;
    float B20 = r1 * tA;
    float sv  = left2 * tA;
    float tB  = t * inv21;
    float B21 = fmaf(right2, tB, sv);
    float B22 = t * tB;

    float t0 = B20 * inv30;
    b[0] = r1 * t0;
    sv   = left3 * t0;
    float t1 = B21 * inv31;
    b[1] = fmaf(right2, t1, sv);
    sv   = left2 * t1;
    float t2 = B22 * inv32;
    b[2] = fmaf(right3, t2, sv);
    b[3] = t * t2;

    d[0] = -t0;
    d[1] = t0 - t1;
    d[2] = t1 - t2;
    d[3] = t2;

    si_out = si;
}

__device__ __forceinline__ void eval_point(const float* __restrict__ scp,
                                           float u, float v,
                                           float3& pt, float3& nr)
{
    float bu[4], du[4], bv[4], dv[4];
    int su, svi;
    eval_basis(u, bu, du, su);
    eval_basis(v, bv, dv, svi);

    float px = 0.f, py = 0.f, pz = 0.f;
    float ax = 0.f, ay = 0.f, az = 0.f;
    float cx = 0.f, cy = 0.f, cz = 0.f;

    const int m = svi & 3;
    // float index divisible by 4 by construction
    const float4* base = reinterpret_cast<const float4*>(
        scp + (m * NCP + su) * RSTRIDE + m + 3 * svi);

#pragma unroll
    for (int i = 0; i < 4; i++) {
        const float4* r = base + i * (RSTRIDE / 4);
        float4 f0 = r[0];
        float4 f1 = r[1];
        float4 f2 = r[2];
        // f0 = x0 y0 z0 x1 | f1 = y1 z1 x2 y2 | f2 = z2 x3 y3 z3

        float rx = fmaf(bv[3], f2.y, fmaf(bv[2], f1.z, fmaf(bv[1], f0.w, bv[0] * f0.x)));
        float ry = fmaf(bv[3], f2.z, fmaf(bv[2], f1.w, fmaf(bv[1], f1.x, bv[0] * f0.y)));
        float rz = fmaf(bv[3], f2.w, fmaf(bv[2], f2.x, fmaf(bv[1], f1.y, bv[0] * f0.z)));
        float qx = fmaf(dv[3], f2.y, fmaf(dv[2], f1.z, fmaf(dv[1], f0.w, dv[0] * f0.x)));
        float qy = fmaf(dv[3], f2.z, fmaf(dv[2], f1.w, fmaf(dv[1], f1.x, dv[0] * f0.y)));
        float qz = fmaf(dv[3], f2.w, fmaf(dv[2], f2.x, fmaf(dv[1], f1.y, dv[0] * f0.z)));

        px = fmaf(bu[i], rx, px);
        py = fmaf(bu[i], ry, py);
        pz = fmaf(bu[i], rz, pz);
        ax = fmaf(du[i], rx, ax);
        ay = fmaf(du[i], ry, ay);
        az = fmaf(du[i], rz, az);
        cx = fmaf(bu[i], qx, cx);
        cy = fmaf(bu[i], qy, cy);
        cz = fmaf(bu[i], qz, cz);
    }

    float nx = fmaf(ay, cz, -(az * cy));
    float ny = fmaf(az, cx, -(ax * cz));
    float nz = fmaf(ax, cy, -(ay * cx));

    float n2 = fmaf(nx, nx, fmaf(ny, ny, nz * nz));
    n2 = fmaxf(n2, 1.0e-30f);
    float h = 0.5f * n2;
    float y = __uint_as_float(0x5f3759dfu - (__float_as_uint(n2) >> 1));
    y = y * fmaf(-h, y * y, 1.5f);
    y = y * fmaf(-h, y * y, 1.5f);

    pt = make_float3(px, py, pz);
    nr = make_float3(nx * y, ny * y, nz * y);
}

__global__ __launch_bounds__(TPB, 4)
void nurbs_kernel(const float* __restrict__ ev,
                  const float* __restrict__ cp,
                  float* __restrict__ out,
                  int P)
{
    extern __shared__ float scp[];   // [4 copies][32 rows][RSTRIDE]

    const int sf = blockIdx.y;
    const float* cpb = cp + (size_t)sf * (NCP * NCP * 3);

    // Stage CPs: packed xyz rows, 4 shifted copies for LDS.128 alignment.
    // Amortized over ~11K points by the persistent loop below.
    for (int k = threadIdx.x; k < NCP * NCP; k += TPB) {
        int iu = k >> 5;
        int iv = k & 31;
        float x = cpb[3 * k + 0];
        float y = cpb[3 * k + 1];
        float z = cpb[3 * k + 2];
#pragma unroll
        for (int m = 0; m < 4; m++) {
            float* row = scp + (m * NCP + iu) * RSTRIDE + m + 3 * iv;
            row[0] = x; row[1] = y; row[2] = z;
        }
    }
    __syncthreads();

    const size_t slice = (size_t)sf * P;

    // chunk: points per block, multiple of 2*TPB so iterations stay aligned
    const int step  = 2 * TPB;                       // points per iteration
    const int chunk = ((P + (int)gridDim.x - 1) / (int)gridDim.x + step - 1)
                      / step * step;
    const int pbeg = blockIdx.x * chunk;
    const int pend = min(P, pbeg + chunk);

    for (int p0 = pbeg + (int)threadIdx.x * 2; p0 < pend; p0 += step) {
        // 16B-aligned: (slice + p0) even
        float4 e = *reinterpret_cast<const float4*>(ev + (slice + p0) * 2);

        float3 pt0, nr0, pt1, nr1;
        eval_point(scp, e.x, e.y, pt0, nr0);
        eval_point(scp, e.z, e.w, pt1, nr1);

        // 6 floats per array per thread; (slice+p0)*3 is even -> 8B aligned
        float2* po = reinterpret_cast<float2*>(out + (slice + p0) * 3);
        po[0] = make_float2(pt0.x, pt0.y);
        po[1] = make_float2(pt0.z, pt1.x);
        po[2] = make_float2(pt1.y, pt1.z);
        float2* pn = reinterpret_cast<float2*>(out + (size_t)SFCOUNT * P * 3 +
                                               (slice + p0) * 3);
        pn[0] = make_float2(nr0.x, nr0.y);
        pn[1] = make_float2(nr0.z, nr1.x);
        pn[2] = make_float2(nr1.y, nr1.z);
    }
}

extern "C" void kernel_launch(void* const* d_in, const int* in_sizes, int n_in,
                              void* d_out, int out_size)
{
    const float* ev = (const float*)d_in[0];   // [S,F,P,2] f32
    const float* cp = (const float*)d_in[1];   // [S,F,32,32,3] f32
    float* out = (float*)d_out;                // [2,S,F,P,3] f32 (pt, normals)

    const int P = in_sizes[0] / (SFCOUNT * 2);

    // Host-side attribute set; run once (not re-issued under graph capture).
    static bool attr_done = false;
    if (!attr_done) {
        cudaFuncSetAttribute(nurbs_kernel,
                             cudaFuncAttributeMaxDynamicSharedMemorySize,
                             (int)SMEMSZ);
        attr_done = true;
    }

    dim3 grid(NBX, SFCOUNT);
    nurbs_kernel<<<grid, TPB, SMEMSZ>>>(ev, cp, out, P);
}